// round 1
// baseline (speedup 1.0000x reference)
#include <cuda_runtime.h>
#include <math.h>

#define HW    9216
#define CH    256
#define NB    2
#define IMG   96

// ---------------- scratch (static device globals; no allocation) ----------------
__device__ float g_lpart[8ull * 8 * 9 * HW];     // [chunk(8)][n*4+br(8)][o(9)][HW] partial logits
__device__ float g_f[8ull * 9 * HW];             // [n*4+br][o][HW] softmax tap weights
__device__ float g_z[10ull * CH * HW];           // [b(5)*2+n][c][HW]  z_b = W_b @ x
__device__ float g_y[(size_t)NB * CH * HW];      // pre-GN output
__device__ float g_bpart[NB * 96 * 64];          // [n][row][group*2+{sum,sq}]
__device__ float g_stats[NB * 32 * 2];           // [n][group][{mean,rstd}]

// ---------------- 1) dilated 3x3 conv C->9 logits, per channel-chunk partials ----------------
// grid: (9 tiles of 32x32, 8 = n*4+br, 8 channel chunks of 32), block 128
__global__ void __launch_bounds__(128) logits_kernel(
    const float* __restrict__ x,
    const float* __restrict__ wa, const float* __restrict__ wbr,
    const float* __restrict__ wc, const float* __restrict__ wd)
{
    int tileId = blockIdx.x;
    int by = tileId / 3, bx = tileId - 3 * by;
    int nb = blockIdx.y;                // n*4+br
    int n  = nb >> 2, br = nb & 3;
    int chunk = blockIdx.z;

    int D = (br == 0) ? 1 : (br == 1) ? 4 : (br == 2) ? 8 : 12;
    const float* w = (br == 0) ? wa : (br == 1) ? wbr : (br == 2) ? wc : wd;
    int S = 32 + 2 * D;                 // tile side with halo (max 56)

    __shared__ float xt[56 * 56];
    __shared__ float ws[81];

    int tid = threadIdx.x;
    int lx = tid & 31, lys = tid >> 5;  // lys 0..3; rows lys + 4*r
    int oy0 = by * 32, ox0 = bx * 32;

    float acc[9][8];
#pragma unroll
    for (int o = 0; o < 9; o++)
#pragma unroll
        for (int r = 0; r < 8; r++) acc[o][r] = 0.f;

    int c0 = chunk * 32;
    for (int ci = 0; ci < 32; ci++) {
        int c = c0 + ci;
        const float* xc = x + ((size_t)n * CH + c) * HW;
        int SS = S * S;
        for (int idx = tid; idx < SS; idx += 128) {
            int ty = idx / S, tx = idx - ty * S;
            int gy = oy0 - D + ty, gx = ox0 - D + tx;
            float v = 0.f;
            if ((unsigned)gy < 96u && (unsigned)gx < 96u) v = xc[gy * 96 + gx];
            xt[idx] = v;
        }
        if (tid < 81) ws[tid] = w[((tid / 9) * CH + c) * 9 + (tid % 9)];
        __syncthreads();

#pragma unroll
        for (int t = 0; t < 9; t++) {
            int ii = t / 3, jj = t % 3;
            int base = (lys + ii * D) * S + lx + jj * D;
            float xv[8];
#pragma unroll
            for (int r = 0; r < 8; r++) xv[r] = xt[base + r * 4 * S];
#pragma unroll
            for (int o = 0; o < 9; o++) {
                float wv = ws[o * 9 + t];
#pragma unroll
                for (int r = 0; r < 8; r++) acc[o][r] = fmaf(wv, xv[r], acc[o][r]);
            }
        }
        __syncthreads();
    }

    size_t outBase = ((size_t)chunk * 8 + nb) * (9 * HW);
#pragma unroll
    for (int o = 0; o < 9; o++)
#pragma unroll
        for (int r = 0; r < 8; r++)
            g_lpart[outBase + o * HW + (oy0 + lys + r * 4) * 96 + ox0 + lx] = acc[o][r];
}

// ---------------- 2) reduce chunks + softmax over 9 taps ----------------
__global__ void __launch_bounds__(256) softmax_kernel()
{
    int id = blockIdx.x * 256 + threadIdx.x;     // 73728 = 8 * HW
    int p = id % HW;
    int nb = id / HW;                            // n*4+br
    float l[9];
#pragma unroll
    for (int o = 0; o < 9; o++) {
        float s = 0.f;
#pragma unroll
        for (int ck = 0; ck < 8; ck++)
            s += g_lpart[((size_t)ck * 8 + nb) * (9 * HW) + o * HW + p];
        l[o] = s;
    }
    float m = l[0];
#pragma unroll
    for (int o = 1; o < 9; o++) m = fmaxf(m, l[o]);
    float s = 0.f;
#pragma unroll
    for (int o = 0; o < 9; o++) { l[o] = expf(l[o] - m); s += l[o]; }
    float inv = 1.f / s;
#pragma unroll
    for (int o = 0; o < 9; o++)
        g_f[((size_t)nb * 9 + o) * HW + p] = l[o] * inv;
}

// ---------------- 3) z_b = W_b @ x : 10 GEMMs 256x9216x256 ----------------
// grid (72, 4, 10), block 256; BM=64(co) BN=128(px) BK=16; thread: 4x8
__global__ void __launch_bounds__(256) gemm_kernel(
    const float* __restrict__ x, const float* __restrict__ wproj)
{
    int pt = blockIdx.x;
    int mt = blockIdx.y;
    int b  = blockIdx.z >> 1;
    int n  = blockIdx.z & 1;

    const float* A = wproj + mt * 64 * 1280 + b * 256;       // [m][k] stride 1280
    const float* B = x + (size_t)n * CH * HW + pt * 128;     // [k][p] stride HW
    float* C = g_z + ((size_t)(b * 2 + n) * CH + mt * 64) * HW + pt * 128;

    __shared__ float As[16][64];
    __shared__ float Bs[16][128];

    int tid = threadIdx.x;
    int am = tid >> 2, ak = (tid & 3) << 2;
    int bk = tid >> 4, bp = (tid & 15) << 3;
    int tm = (tid >> 4) << 2;
    int tn = (tid & 15) << 3;

    float acc[4][8];
#pragma unroll
    for (int m = 0; m < 4; m++)
#pragma unroll
        for (int p2 = 0; p2 < 8; p2++) acc[m][p2] = 0.f;

    for (int k0 = 0; k0 < 256; k0 += 16) {
        float4 av = *(const float4*)(A + am * 1280 + k0 + ak);
        As[ak + 0][am] = av.x; As[ak + 1][am] = av.y;
        As[ak + 2][am] = av.z; As[ak + 3][am] = av.w;
        const float* Bp = B + (size_t)(k0 + bk) * HW + bp;
        *(float4*)&Bs[bk][bp]     = *(const float4*)(Bp);
        *(float4*)&Bs[bk][bp + 4] = *(const float4*)(Bp + 4);
        __syncthreads();
#pragma unroll
        for (int kk = 0; kk < 16; kk++) {
            float ar[4], brv[8];
            *(float4*)ar        = *(const float4*)&As[kk][tm];
            *(float4*)brv       = *(const float4*)&Bs[kk][tn];
            *(float4*)(brv + 4) = *(const float4*)&Bs[kk][tn + 4];
#pragma unroll
            for (int m = 0; m < 4; m++)
#pragma unroll
                for (int p2 = 0; p2 < 8; p2++)
                    acc[m][p2] = fmaf(ar[m], brv[p2], acc[m][p2]);
        }
        __syncthreads();
    }
#pragma unroll
    for (int m = 0; m < 4; m++) {
        float* Cr = C + (size_t)(tm + m) * HW + tn;
        *(float4*)Cr       = make_float4(acc[m][0], acc[m][1], acc[m][2], acc[m][3]);
        *(float4*)(Cr + 4) = make_float4(acc[m][4], acc[m][5], acc[m][6], acc[m][7]);
    }
}

// ---------------- 4) combine: y = z0 + sum_b sum_k f * z_b(shifted) + bias; GN partials ----------------
// grid (96 rows, 2 n), block 384 = 96 x * 4 csub (each csub owns 64 contiguous channels)
__global__ void __launch_bounds__(384) combine_kernel(const float* __restrict__ bias)
{
    int yrow = blockIdx.x, n = blockIdx.y;
    int tid = threadIdx.x;
    int xcol = tid % 96, csub = tid / 96;

    __shared__ float fs[36 * 96];       // [br*9+k][x]
    __shared__ float wred[12][16];      // per-warp group partials [warp][gi*2+{s,q}]

    for (int i = tid; i < 36 * 96; i += 384) {
        int brk = i / 96, xx = i - brk * 96;
        fs[i] = g_f[((size_t)n * 36 + brk) * HW + yrow * 96 + xx];
    }
    __syncthreads();

    const int dil[4] = {1, 4, 8, 12};
    int p = yrow * 96 + xcol;

    float fw[36];
    int   zof[36];
    {
        int idx = 0;
#pragma unroll
        for (int br = 0; br < 4; br++) {
            int d = dil[br];
            int sliceOff = ((br + 1) * 2 + n) * (CH * HW);
#pragma unroll
            for (int k = 0; k < 9; k++) {
                int yy = yrow + (k / 3 - 1) * d;
                int xx = xcol + (k % 3 - 1) * d;
                bool v = ((unsigned)yy < 96u) && ((unsigned)xx < 96u);
                fw[idx]  = v ? fs[(br * 9 + k) * 96 + xcol] : 0.f;
                zof[idx] = sliceOff + (v ? (yy * 96 + xx) : 0);
                idx++;
            }
        }
    }

    float gsum[8], gsq[8];
#pragma unroll
    for (int gi = 0; gi < 8; gi++) {
        float s = 0.f, q = 0.f;
        for (int i2 = 0; i2 < 8; i2++) {
            int c = csub * 64 + gi * 8 + i2;
            int cb = c * HW;
            float acc = g_z[(size_t)(n * CH + c) * HW + p] + bias[c];
#pragma unroll
            for (int j = 0; j < 36; j++)
                acc = fmaf(fw[j], g_z[(size_t)zof[j] + cb], acc);
            g_y[(size_t)(n * CH + c) * HW + p] = acc;
            s += acc; q += acc * acc;
        }
        gsum[gi] = s; gsq[gi] = q;
    }

    // deterministic reduction: warp shuffles -> per-warp smem -> 3-warp sum per csub
    int wp = tid >> 5, lane = tid & 31;
#pragma unroll
    for (int gi = 0; gi < 8; gi++) {
        float s = gsum[gi], q = gsq[gi];
#pragma unroll
        for (int off = 16; off > 0; off >>= 1) {
            s += __shfl_xor_sync(0xffffffffu, s, off);
            q += __shfl_xor_sync(0xffffffffu, q, off);
        }
        if (lane == 0) { wred[wp][gi * 2] = s; wred[wp][gi * 2 + 1] = q; }
    }
    __syncthreads();
    if (tid < 64) {
        int g = tid >> 1, isq = tid & 1;
        int cs = g >> 3, gi = g & 7;
        float v = wred[cs * 3 + 0][gi * 2 + isq]
                + wred[cs * 3 + 1][gi * 2 + isq]
                + wred[cs * 3 + 2][gi * 2 + isq];
        g_bpart[(n * 96 + yrow) * 64 + tid] = v;
    }
}

// ---------------- 5) GN stats ----------------
__global__ void stats_kernel()
{
    int t = threadIdx.x;            // 0..63 : n*32+g
    float s = 0.f, q = 0.f;
    int n = t >> 5, g = t & 31;
    for (int r = 0; r < 96; r++) {
        s += g_bpart[(n * 96 + r) * 64 + g * 2];
        q += g_bpart[(n * 96 + r) * 64 + g * 2 + 1];
    }
    const float invN = 1.f / 73728.f;
    float mean = s * invN;
    float var  = q * invN - mean * mean;
    g_stats[t * 2]     = mean;
    g_stats[t * 2 + 1] = rsqrtf(var + 1e-5f);
}

// ---------------- 6) normalize + affine + relu ----------------
__global__ void __launch_bounds__(256) norm_kernel(
    const float* __restrict__ gamma, const float* __restrict__ beta,
    float* __restrict__ out)
{
    int i4 = blockIdx.x * 256 + threadIdx.x;   // 1179648 float4s
    size_t e = (size_t)i4 * 4;
    int n = (int)(e / ((size_t)CH * HW));
    int c = (int)((e / HW) & 255);
    int g = c >> 3;
    float mean = g_stats[(n * 32 + g) * 2];
    float rstd = g_stats[(n * 32 + g) * 2 + 1];
    float ga = gamma[c] * rstd;
    float be = beta[c] - mean * ga;
    float4 v = *(const float4*)&g_y[e];
    v.x = fmaxf(fmaf(v.x, ga, be), 0.f);
    v.y = fmaxf(fmaf(v.y, ga, be), 0.f);
    v.z = fmaxf(fmaf(v.z, ga, be), 0.f);
    v.w = fmaxf(fmaf(v.w, ga, be), 0.f);
    *(float4*)((float*)out + e) = v;
}

// ---------------- launch ----------------
extern "C" void kernel_launch(void* const* d_in, const int* in_sizes, int n_in,
                              void* d_out, int out_size)
{
    const float* x     = (const float*)d_in[0];
    const float* wa    = (const float*)d_in[1];
    const float* wb    = (const float*)d_in[2];
    const float* wc    = (const float*)d_in[3];
    const float* wd    = (const float*)d_in[4];
    const float* wproj = (const float*)d_in[5];
    const float* bproj = (const float*)d_in[6];
    const float* gamma = (const float*)d_in[7];
    const float* beta  = (const float*)d_in[8];
    float* out = (float*)d_out;

    logits_kernel<<<dim3(9, 8, 8), 128>>>(x, wa, wb, wc, wd);
    softmax_kernel<<<288, 256>>>();
    gemm_kernel<<<dim3(72, 4, 10), 256>>>(x, wproj);
    combine_kernel<<<dim3(96, 2), 384>>>(bproj);
    stats_kernel<<<1, 64>>>();
    norm_kernel<<<4608, 256>>>(gamma, beta, out);
}

// round 3
// speedup vs baseline: 1.3388x; 1.3388x over previous
#include <cuda_runtime.h>
#include <cuda_bf16.h>
#include <cstdint>
#include <math.h>

#define HW    9216
#define CH    256
#define NB    2

// ---------------- scratch ----------------
__device__ float g_lpart[8ull * 8 * 9 * HW];       // [chunk][n*4+br][o][HW] partial logits
__device__ float g_f[8ull * 9 * HW];               // [n*4+br][o][HW] softmax tap weights
__device__ float g_z[10ull * HW * CH + 400000];    // [b*2+n][p][c] (+pad for shifted reads)
__device__ float g_y[(size_t)NB * HW * CH];        // [n][p][c] pre-GN output
__device__ float g_bpart[NB * 96 * 64];
__device__ float g_stats[NB * 32 * 2];
__device__ __nv_bfloat16 g_w[10ull * 256 * 256];   // [b*2+sel][m][k]  sel0=hi sel1=lo
__device__ __nv_bfloat16 g_xT[4ull * HW * 256];    // [n*2+sel][p][k]

// ---------------- helpers ----------------
__device__ __forceinline__ uint32_t smem_u32(const void* p) {
    uint32_t a;
    asm("{ .reg .u64 t; cvta.to.shared.u64 t, %1; cvt.u32.u64 %0, t; }" : "=r"(a) : "l"(p));
    return a;
}
__device__ __forceinline__ void ldmatrix_x4(uint32_t& r0, uint32_t& r1, uint32_t& r2, uint32_t& r3, uint32_t addr) {
    asm volatile("ldmatrix.sync.aligned.m8n8.x4.shared.b16 {%0,%1,%2,%3}, [%4];"
        : "=r"(r0), "=r"(r1), "=r"(r2), "=r"(r3) : "r"(addr));
}
__device__ __forceinline__ void mma_bf16(float* c, const uint32_t* a, uint32_t b0, uint32_t b1) {
    asm volatile("mma.sync.aligned.m16n8k16.row.col.f32.bf16.bf16.f32 "
        "{%0,%1,%2,%3}, {%4,%5,%6,%7}, {%8,%9}, {%0,%1,%2,%3};"
        : "+f"(c[0]), "+f"(c[1]), "+f"(c[2]), "+f"(c[3])
        : "r"(a[0]), "r"(a[1]), "r"(a[2]), "r"(a[3]), "r"(b0), "r"(b1));
}
__device__ __forceinline__ void cp_async16(uint32_t saddr, const void* gaddr) {
    asm volatile("cp.async.cg.shared.global [%0], [%1], 16;" :: "r"(saddr), "l"(gaddr));
}

// ---------------- prep: split W into bf16 hi/lo ----------------
__global__ void __launch_bounds__(256) wsplit_kernel(const float* __restrict__ wproj)
{
    int idx = blockIdx.x * 256 + threadIdx.x;          // 5*65536
    if (idx >= 5 * 65536) return;
    int b = idx >> 16, rem = idx & 65535;
    int m = rem >> 8, k = rem & 255;
    float w = wproj[m * 1280 + b * 256 + k];
    __nv_bfloat16 hi = __float2bfloat16(w);
    __nv_bfloat16 lo = __float2bfloat16(w - __bfloat162float(hi));
    g_w[((size_t)(b * 2 + 0) * 256 + m) * 256 + k] = hi;
    g_w[((size_t)(b * 2 + 1) * 256 + m) * 256 + k] = lo;
}

// ---------------- prep: transpose x to [p][k] + bf16 hi/lo ----------------
__global__ void __launch_bounds__(256) xsplit_kernel(const float* __restrict__ x)
{
    __shared__ float t[32][33];
    int p0 = blockIdx.x * 32, k0 = blockIdx.y * 32, n = blockIdx.z;
    int tx = threadIdx.x, ty = threadIdx.y;
#pragma unroll
    for (int r = 0; r < 4; r++)
        t[ty + 8 * r][tx] = x[((size_t)(n * 256 + k0 + ty + 8 * r)) * HW + p0 + tx];
    __syncthreads();
#pragma unroll
    for (int r = 0; r < 4; r++) {
        int p = p0 + ty + 8 * r, k = k0 + tx;
        float v = t[tx][ty + 8 * r];
        __nv_bfloat16 hi = __float2bfloat16(v);
        __nv_bfloat16 lo = __float2bfloat16(v - __bfloat162float(hi));
        g_xT[((size_t)(n * 2 + 0) * HW + p) * 256 + k] = hi;
        g_xT[((size_t)(n * 2 + 1) * HW + p) * 256 + k] = lo;
    }
}

// ---------------- 1) dilated 3x3 conv C->9 logits ----------------
__global__ void __launch_bounds__(128) logits_kernel(
    const float* __restrict__ x,
    const float* __restrict__ wa, const float* __restrict__ wbr,
    const float* __restrict__ wc, const float* __restrict__ wd)
{
    int tileId = blockIdx.x;
    int by = tileId / 3, bx = tileId - 3 * by;
    int nb = blockIdx.y;
    int n  = nb >> 2, br = nb & 3;
    int chunk = blockIdx.z;

    int D = (br == 0) ? 1 : (br == 1) ? 4 : (br == 2) ? 8 : 12;
    const float* w = (br == 0) ? wa : (br == 1) ? wbr : (br == 2) ? wc : wd;
    int S = 32 + 2 * D;

    __shared__ float xt[56 * 56];
    __shared__ float ws[81];

    int tid = threadIdx.x;
    int lx = tid & 31, lys = tid >> 5;
    int oy0 = by * 32, ox0 = bx * 32;

    float acc[9][8];
#pragma unroll
    for (int o = 0; o < 9; o++)
#pragma unroll
        for (int r = 0; r < 8; r++) acc[o][r] = 0.f;

    int c0 = chunk * 32;
    for (int ci = 0; ci < 32; ci++) {
        int c = c0 + ci;
        const float* xc = x + ((size_t)n * CH + c) * HW;
        int SS = S * S;
        for (int idx = tid; idx < SS; idx += 128) {
            int ty = idx / S, tx = idx - ty * S;
            int gy = oy0 - D + ty, gx = ox0 - D + tx;
            float v = 0.f;
            if ((unsigned)gy < 96u && (unsigned)gx < 96u) v = xc[gy * 96 + gx];
            xt[idx] = v;
        }
        if (tid < 81) ws[tid] = w[((tid / 9) * CH + c) * 9 + (tid % 9)];
        __syncthreads();

#pragma unroll
        for (int t = 0; t < 9; t++) {
            int ii = t / 3, jj = t % 3;
            int base = (lys + ii * D) * S + lx + jj * D;
            float xv[8];
#pragma unroll
            for (int r = 0; r < 8; r++) xv[r] = xt[base + r * 4 * S];
#pragma unroll
            for (int o = 0; o < 9; o++) {
                float wv = ws[o * 9 + t];
#pragma unroll
                for (int r = 0; r < 8; r++) acc[o][r] = fmaf(wv, xv[r], acc[o][r]);
            }
        }
        __syncthreads();
    }

    size_t outBase = ((size_t)chunk * 8 + nb) * (9 * HW);
#pragma unroll
    for (int o = 0; o < 9; o++)
#pragma unroll
        for (int r = 0; r < 8; r++)
            g_lpart[outBase + o * HW + (oy0 + lys + r * 4) * 96 + ox0 + lx] = acc[o][r];
}

// ---------------- 2) softmax over 9 taps ----------------
__global__ void __launch_bounds__(256) softmax_kernel()
{
    int id = blockIdx.x * 256 + threadIdx.x;
    int p = id % HW;
    int nb = id / HW;
    float l[9];
#pragma unroll
    for (int o = 0; o < 9; o++) {
        float s = 0.f;
#pragma unroll
        for (int ck = 0; ck < 8; ck++)
            s += g_lpart[((size_t)ck * 8 + nb) * (9 * HW) + o * HW + p];
        l[o] = s;
    }
    float m = l[0];
#pragma unroll
    for (int o = 1; o < 9; o++) m = fmaxf(m, l[o]);
    float s = 0.f;
#pragma unroll
    for (int o = 0; o < 9; o++) { l[o] = expf(l[o] - m); s += l[o]; }
    float inv = 1.f / s;
#pragma unroll
    for (int o = 0; o < 9; o++)
        g_f[((size_t)nb * 9 + o) * HW + p] = l[o] * inv;
}

// ---------------- 3) HMMA bf16 GEMM (3-term hi/lo split) ----------------
// grid (72 p-tiles, 2 m-tiles, 10 b*2+n), block 256 (8 warps, 2x4 warp grid)
// C[128m,128p] = sum over 12 chunks of 64k: W_chunk @ X_chunk
__global__ void __launch_bounds__(256, 2) gemm_mma_kernel()
{
    extern __shared__ char dsm[];            // 0..16K A0 | 16K B0 | 32K A1 | 48K B1 ; epilogue: stage
    int tid = threadIdx.x;
    int wid = tid >> 5, lane = tid & 31;
    int pbase = blockIdx.x * 128;
    int mbase = blockIdx.y * 128;
    int bn = blockIdx.z;
    int b = bn >> 1, n = bn & 1;
    int warp_m = wid & 1, warp_n = wid >> 1;

    uint32_t sbase = smem_u32(dsm);
    const uint32_t offA[2] = { 0u, 32768u };
    const uint32_t offB[2] = { 16384u, 49152u };

    float acc[4][4][4];
#pragma unroll
    for (int i = 0; i < 4; i++)
#pragma unroll
        for (int j = 0; j < 4; j++)
#pragma unroll
            for (int r = 0; r < 4; r++) acc[i][j][r] = 0.f;

    auto issue = [&](int i) {
        int buf = i & 1;
        int seg = i >> 2, kc = i & 3;
        int aSel = (seg == 1) ? 1 : 0;
        int bSel = (seg == 2) ? 1 : 0;
        const char* Ag = (const char*)g_w  + ((size_t)((b * 2 + aSel) * 256 + mbase)) * 512 + kc * 128;
        const char* Bg = (const char*)g_xT + ((size_t)((n * 2 + bSel) * HW + pbase)) * 512 + kc * 128;
#pragma unroll
        for (int r = 0; r < 4; r++) {
            int idx = tid + 256 * r;          // 0..1023
            int row = idx >> 3, u = idx & 7;
            uint32_t sw = row * 128 + ((u ^ (row & 7)) << 4);
            cp_async16(sbase + offA[buf] + sw, Ag + (size_t)row * 512 + u * 16);
            cp_async16(sbase + offB[buf] + sw, Bg + (size_t)row * 512 + u * 16);
        }
        asm volatile("cp.async.commit_group;");
    };

    auto compute = [&](int buf) {
        uint32_t aB = sbase + offA[buf];
        uint32_t bB = sbase + offB[buf];
#pragma unroll
        for (int ks = 0; ks < 4; ks++) {
            int u0 = ks * 2 + (lane >> 4);
            uint32_t a[4][4], bb[2][4];
#pragma unroll
            for (int mi = 0; mi < 4; mi++) {
                int row = warp_m * 64 + mi * 16 + (lane & 15);
                uint32_t ad = aB + row * 128 + (((unsigned)(u0 ^ (row & 7))) << 4);
                ldmatrix_x4(a[mi][0], a[mi][1], a[mi][2], a[mi][3], ad);
            }
#pragma unroll
            for (int q = 0; q < 2; q++) {
                int row = warp_n * 32 + q * 16 + (lane & 15);
                uint32_t bd = bB + row * 128 + (((unsigned)(u0 ^ (row & 7))) << 4);
                ldmatrix_x4(bb[q][0], bb[q][1], bb[q][2], bb[q][3], bd);
            }
#pragma unroll
            for (int mi = 0; mi < 4; mi++)
#pragma unroll
                for (int nj = 0; nj < 4; nj++) {
                    int q = nj >> 1, pr = nj & 1;
                    mma_bf16(acc[mi][nj], a[mi], bb[q][pr], bb[q][pr + 2]);
                }
        }
    };

    issue(0);
    for (int i = 0; i < 12; i++) {
        if (i < 11) {
            issue(i + 1);
            asm volatile("cp.async.wait_group 1;");
        } else {
            asm volatile("cp.async.wait_group 0;");
        }
        __syncthreads();
        compute(i & 1);
        __syncthreads();
    }

    // epilogue: acc -> stage[p][m] (pad 132) -> coalesced STG to g_z[bn][p][c]
    float* stage = (float*)dsm;
#pragma unroll
    for (int mi = 0; mi < 4; mi++)
#pragma unroll
        for (int nj = 0; nj < 4; nj++)
#pragma unroll
            for (int r = 0; r < 4; r++) {
                int p = warp_n * 32 + nj * 8 + 2 * (lane & 3) + (r & 1);
                int m = warp_m * 64 + mi * 16 + (lane >> 2) + ((r >> 1) << 3);
                stage[p * 132 + m] = acc[mi][nj][r];
            }
    __syncthreads();
    float* zo = (float*)g_z + ((size_t)bn * HW + pbase) * 256 + mbase;
#pragma unroll
    for (int r = 0; r < 16; r++) {
        int idx = tid + 256 * r;              // 0..4095
        int px = idx >> 5, c4 = (idx & 31) * 4;
        float4 v = *(float4*)&stage[px * 132 + c4];
        *(float4*)(zo + (size_t)px * 256 + c4) = v;
    }
}

// ---------------- 4) combine + GN partials (z layout [p][c]) ----------------
__global__ void __launch_bounds__(384) combine_kernel(const float* __restrict__ bias)
{
    int yrow = blockIdx.x, n = blockIdx.y;
    int tid = threadIdx.x;
    int xcol = tid % 96, csub = tid / 96;

    __shared__ float fsw[36 * 96];
    __shared__ float wred[12][16];

    for (int i = tid; i < 36 * 96; i += 384) {
        int j = i / 96, xx = i - j * 96;
        int br = j / 9, k = j - br * 9;
        int d = (br == 0) ? 1 : (br == 1) ? 4 : (br == 2) ? 8 : 12;
        int yy = yrow + (k / 3 - 1) * d;
        int xv = xx + (k % 3 - 1) * d;
        bool valid = ((unsigned)yy < 96u) && ((unsigned)xv < 96u);
        fsw[i] = valid ? g_f[((size_t)(n * 4 + br) * 9 + k) * HW + yrow * 96 + xx] : 0.f;
    }
    __syncthreads();

    int p = yrow * 96 + xcol;
    const float* z0 = g_z + ((size_t)n * HW + p) * 256 + csub * 64;
    const float* zb[4];
#pragma unroll
    for (int br = 0; br < 4; br++)
        zb[br] = g_z + ((size_t)((br + 1) * 2 + n) * HW + p) * 256 + csub * 64;
    float* yo = g_y + ((size_t)n * HW + p) * 256 + csub * 64;
    const float* bi = bias + csub * 64;

    float gsum[8], gsq[8];
#pragma unroll 1
    for (int gi = 0; gi < 8; gi++) {
        float a0, a1, a2, a3, a4, a5, a6, a7;
        {
            float4 v0 = *(const float4*)(z0 + gi * 8);
            float4 v1 = *(const float4*)(z0 + gi * 8 + 4);
            float4 b0 = *(const float4*)(bi + gi * 8);
            float4 b1 = *(const float4*)(bi + gi * 8 + 4);
            a0 = v0.x + b0.x; a1 = v0.y + b0.y; a2 = v0.z + b0.z; a3 = v0.w + b0.w;
            a4 = v1.x + b1.x; a5 = v1.y + b1.y; a6 = v1.z + b1.z; a7 = v1.w + b1.w;
        }
#pragma unroll
        for (int br = 0; br < 4; br++) {
            const int d = (br == 0) ? 1 : (br == 1) ? 4 : (br == 2) ? 8 : 12;
            const float* zbr = zb[br] + gi * 8;
#pragma unroll
            for (int k = 0; k < 9; k++) {
                const int delta = ((k / 3 - 1) * 96 + (k % 3 - 1)) * d * 256;
                float f = fsw[(br * 9 + k) * 96 + xcol];
                float4 v0 = *(const float4*)(zbr + delta);
                float4 v1 = *(const float4*)(zbr + delta + 4);
                a0 = fmaf(f, v0.x, a0); a1 = fmaf(f, v0.y, a1);
                a2 = fmaf(f, v0.z, a2); a3 = fmaf(f, v0.w, a3);
                a4 = fmaf(f, v1.x, a4); a5 = fmaf(f, v1.y, a5);
                a6 = fmaf(f, v1.z, a6); a7 = fmaf(f, v1.w, a7);
            }
        }
        *(float4*)(yo + gi * 8)     = make_float4(a0, a1, a2, a3);
        *(float4*)(yo + gi * 8 + 4) = make_float4(a4, a5, a6, a7);
        gsum[gi] = a0 + a1 + a2 + a3 + a4 + a5 + a6 + a7;
        gsq[gi]  = a0*a0 + a1*a1 + a2*a2 + a3*a3 + a4*a4 + a5*a5 + a6*a6 + a7*a7;
    }

    int wp = tid >> 5, lane = tid & 31;
#pragma unroll
    for (int gi = 0; gi < 8; gi++) {
        float s = gsum[gi], q = gsq[gi];
#pragma unroll
        for (int off = 16; off > 0; off >>= 1) {
            s += __shfl_xor_sync(0xffffffffu, s, off);
            q += __shfl_xor_sync(0xffffffffu, q, off);
        }
        if (lane == 0) { wred[wp][gi * 2] = s; wred[wp][gi * 2 + 1] = q; }
    }
    __syncthreads();
    if (tid < 64) {
        int g = tid >> 1, isq = tid & 1;
        int cs = g >> 3, gi = g & 7;
        float v = wred[cs * 3 + 0][gi * 2 + isq]
                + wred[cs * 3 + 1][gi * 2 + isq]
                + wred[cs * 3 + 2][gi * 2 + isq];
        g_bpart[(n * 96 + yrow) * 64 + tid] = v;
    }
}

// ---------------- 5) GN stats ----------------
__global__ void stats_kernel()
{
    int t = threadIdx.x;
    float s = 0.f, q = 0.f;
    int n = t >> 5, g = t & 31;
    for (int r = 0; r < 96; r++) {
        s += g_bpart[(n * 96 + r) * 64 + g * 2];
        q += g_bpart[(n * 96 + r) * 64 + g * 2 + 1];
    }
    const float invN = 1.f / 73728.f;
    float mean = s * invN;
    float var  = q * invN - mean * mean;
    g_stats[t * 2]     = mean;
    g_stats[t * 2 + 1] = rsqrtf(var + 1e-5f);
}

// ---------------- 6) transpose [p][c]->[c][p] + GN affine + relu ----------------
__global__ void __launch_bounds__(256) normT_kernel(
    const float* __restrict__ gamma, const float* __restrict__ beta,
    float* __restrict__ out)
{
    __shared__ float t[32][33];
    int p0 = blockIdx.x * 32, c0 = blockIdx.y * 32, n = blockIdx.z;
    int tx = threadIdx.x, ty = threadIdx.y;
#pragma unroll
    for (int r = 0; r < 4; r++)
        t[ty + 8 * r][tx] = g_y[((size_t)n * HW + p0 + ty + 8 * r) * 256 + c0 + tx];
    __syncthreads();
#pragma unroll
    for (int r = 0; r < 4; r++) {
        int c = c0 + ty + 8 * r, p = p0 + tx;
        int g = c >> 3;
        float mean = g_stats[(n * 32 + g) * 2];
        float rstd = g_stats[(n * 32 + g) * 2 + 1];
        float ga = gamma[c] * rstd;
        float be = beta[c] - mean * ga;
        float v = t[tx][ty + 8 * r];
        out[((size_t)n * 256 + c) * HW + p] = fmaxf(fmaf(v, ga, be), 0.f);
    }
}

// ---------------- launch ----------------
extern "C" void kernel_launch(void* const* d_in, const int* in_sizes, int n_in,
                              void* d_out, int out_size)
{
    const float* x     = (const float*)d_in[0];
    const float* wa    = (const float*)d_in[1];
    const float* wb    = (const float*)d_in[2];
    const float* wc    = (const float*)d_in[3];
    const float* wd    = (const float*)d_in[4];
    const float* wproj = (const float*)d_in[5];
    const float* bproj = (const float*)d_in[6];
    const float* gamma = (const float*)d_in[7];
    const float* beta  = (const float*)d_in[8];
    float* out = (float*)d_out;

    cudaFuncSetAttribute(gemm_mma_kernel, cudaFuncAttributeMaxDynamicSharedMemorySize, 69632);

    wsplit_kernel<<<1280, 256>>>(wproj);
    xsplit_kernel<<<dim3(288, 8, 2), dim3(32, 8)>>>(x);
    logits_kernel<<<dim3(9, 8, 8), 128>>>(x, wa, wb, wc, wd);
    softmax_kernel<<<288, 256>>>();
    gemm_mma_kernel<<<dim3(72, 2, 10), 256, 69632>>>();
    combine_kernel<<<dim3(96, 2), 384>>>(bproj);
    stats_kernel<<<1, 64>>>();
    normT_kernel<<<dim3(288, 8, 2), dim3(32, 8)>>>(gamma, beta, out);
}

// round 4
// speedup vs baseline: 2.1186x; 1.5824x over previous
#include <cuda_runtime.h>
#include <cuda_bf16.h>
#include <cstdint>
#include <math.h>

#define HW    9216
#define CH    256
#define NB    2

// ---------------- scratch ----------------
__device__ float g_l[8ull * 9 * HW];               // [nb=n*4+br][o][HW] logits
__device__ float g_f[8ull * 9 * HW];               // [nb][o][HW] softmax tap weights
__device__ float g_z[10ull * HW * CH + 400000];    // [b*2+n][p][c]
__device__ float g_y[(size_t)NB * HW * CH];        // [n][p][c] pre-GN output
__device__ float g_bpart[NB * 1152 * 64];          // [n][blk][group*2+{s,q}]
__device__ float g_stats[NB * 32 * 2];
__device__ __nv_bfloat16 g_w[10ull * 256 * 256];   // [b*2+sel][m][k]
__device__ __nv_bfloat16 g_xT[4ull * HW * 256];    // [n*2+sel][p][k]
__device__ __nv_bfloat16 g_wl[4 * 2 * 9 * 16 * 256]; // [br][sel][tap][m16][k256]

// ---------------- helpers ----------------
__device__ __forceinline__ uint32_t smem_u32(const void* p) {
    uint32_t a;
    asm("{ .reg .u64 t; cvta.to.shared.u64 t, %1; cvt.u32.u64 %0, t; }" : "=r"(a) : "l"(p));
    return a;
}
__device__ __forceinline__ void ldmatrix_x4(uint32_t& r0, uint32_t& r1, uint32_t& r2, uint32_t& r3, uint32_t addr) {
    asm volatile("ldmatrix.sync.aligned.m8n8.x4.shared.b16 {%0,%1,%2,%3}, [%4];"
        : "=r"(r0), "=r"(r1), "=r"(r2), "=r"(r3) : "r"(addr));
}
__device__ __forceinline__ void mma_bf16(float* c, const uint32_t* a, uint32_t b0, uint32_t b1) {
    asm volatile("mma.sync.aligned.m16n8k16.row.col.f32.bf16.bf16.f32 "
        "{%0,%1,%2,%3}, {%4,%5,%6,%7}, {%8,%9}, {%0,%1,%2,%3};"
        : "+f"(c[0]), "+f"(c[1]), "+f"(c[2]), "+f"(c[3])
        : "r"(a[0]), "r"(a[1]), "r"(a[2]), "r"(a[3]), "r"(b0), "r"(b1));
}
__device__ __forceinline__ void cp_async16(uint32_t saddr, const void* gaddr) {
    asm volatile("cp.async.cg.shared.global [%0], [%1], 16;" :: "r"(saddr), "l"(gaddr));
}
__device__ __forceinline__ void cp_async16_sz(uint32_t saddr, const void* gaddr, uint32_t sz) {
    asm volatile("cp.async.cg.shared.global [%0], [%1], 16, %2;" :: "r"(saddr), "l"(gaddr), "r"(sz));
}

// ---------------- prep: split W (proj) into bf16 hi/lo ----------------
__global__ void __launch_bounds__(256) wsplit_kernel(const float* __restrict__ wproj)
{
    int idx = blockIdx.x * 256 + threadIdx.x;
    if (idx >= 5 * 65536) return;
    int b = idx >> 16, rem = idx & 65535;
    int m = rem >> 8, k = rem & 255;
    float w = wproj[m * 1280 + b * 256 + k];
    __nv_bfloat16 hi = __float2bfloat16(w);
    __nv_bfloat16 lo = __float2bfloat16(w - __bfloat162float(hi));
    g_w[((size_t)(b * 2 + 0) * 256 + m) * 256 + k] = hi;
    g_w[((size_t)(b * 2 + 1) * 256 + m) * 256 + k] = lo;
}

// ---------------- prep: split logits weights, pad M 9->16 ----------------
__global__ void __launch_bounds__(256) wlsplit_kernel(
    const float* __restrict__ wa, const float* __restrict__ wb,
    const float* __restrict__ wc, const float* __restrict__ wd)
{
    int idx = blockIdx.x * 256 + threadIdx.x;       // 294912
    if (idx >= 294912) return;
    int k = idx & 255;
    int m = (idx >> 8) & 15;
    int q = idx >> 12;                // q = (br*2+sel)*9 + t
    int t = q % 9;
    int u = q / 9;
    int sel = u & 1, br = u >> 1;
    float w = 0.f;
    if (m < 9) {
        const float* wp = (br == 0) ? wa : (br == 1) ? wb : (br == 2) ? wc : wd;
        w = wp[(m * 256 + k) * 9 + t];
    }
    __nv_bfloat16 hi = __float2bfloat16(w);
    __nv_bfloat16 v = (sel == 0) ? hi : __float2bfloat16(w - __bfloat162float(hi));
    g_wl[(size_t)(q * 16 + m) * 256 + k] = v;
}

// ---------------- prep: transpose x to [p][k] + bf16 hi/lo ----------------
__global__ void __launch_bounds__(256) xsplit_kernel(const float* __restrict__ x)
{
    __shared__ float t[32][33];
    int p0 = blockIdx.x * 32, k0 = blockIdx.y * 32, n = blockIdx.z;
    int tx = threadIdx.x, ty = threadIdx.y;
#pragma unroll
    for (int r = 0; r < 4; r++)
        t[ty + 8 * r][tx] = x[((size_t)(n * 256 + k0 + ty + 8 * r)) * HW + p0 + tx];
    __syncthreads();
#pragma unroll
    for (int r = 0; r < 4; r++) {
        int p = p0 + ty + 8 * r, k = k0 + tx;
        float v = t[tx][ty + 8 * r];
        __nv_bfloat16 hi = __float2bfloat16(v);
        __nv_bfloat16 lo = __float2bfloat16(v - __bfloat162float(hi));
        g_xT[((size_t)(n * 2 + 0) * HW + p) * 256 + k] = hi;
        g_xT[((size_t)(n * 2 + 1) * HW + p) * 256 + k] = lo;
    }
}

// ---------------- 1) logits via HMMA: L[9,HW] += sum taps/terms W_t @ X_shift ----------------
// grid (72 p-tiles, 8 nb), block 128 (4 warps x 32p)
// smem: A[2 sel][4 kc][16m][128B] = 16KB @0 ; B[2 buf][128p][128B] = 32KB @16384
__global__ void __launch_bounds__(128) logits_mma_kernel()
{
    extern __shared__ char dsm[];
    int tid = threadIdx.x;
    int wid = tid >> 5, lane = tid & 31;
    int p0 = blockIdx.x * 128;
    int nb = blockIdx.y;
    int n = nb >> 2, br = nb & 3;
    int d = (br == 0) ? 1 : (br == 1) ? 4 : (br == 2) ? 8 : 12;
    int wn = wid * 32;

    uint32_t sbase = smem_u32(dsm);
    int pg = p0 + tid;
    int y0 = pg / 96, x0 = pg - y0 * 96;

    float acc[4][4];
#pragma unroll
    for (int i = 0; i < 4; i++)
#pragma unroll
        for (int r = 0; r < 4; r++) acc[i][r] = 0.f;

    auto issueB = [&](int it) {
        int tap = it >> 3, r = it & 7;
        int sel = r >> 2, kc = r & 3, buf = it & 1;
        int yy = y0 + (tap / 3 - 1) * d;
        int xx = x0 + (tap % 3 - 1) * d;
        bool valid = ((unsigned)yy < 96u) && ((unsigned)xx < 96u);
        int ps = valid ? (yy * 96 + xx) : 0;
        const char* src = (const char*)g_xT + ((size_t)((n * 2 + sel) * HW + ps)) * 512 + kc * 128;
        uint32_t dst = sbase + 16384u + buf * 16384u + tid * 128u;
        uint32_t sz = valid ? 16u : 0u;
#pragma unroll
        for (int u = 0; u < 8; u++)
            cp_async16_sz(dst + ((u ^ (tid & 7)) << 4), src + u * 16, sz);
        asm volatile("cp.async.commit_group;");
    };

    auto loadA = [&](int tap) {
#pragma unroll
        for (int r = 0; r < 8; r++) {
            int idx = tid + 128 * r;              // 0..1023
            int sel = idx >> 9;
            int rem = idx & 511;
            int row = rem >> 5, u32v = rem & 31;
            int kc = u32v >> 3, u = u32v & 7;
            const __nv_bfloat16* src = g_wl + (size_t)(((br * 2 + sel) * 9 + tap) * 16 + row) * 256 + u32v * 8;
            uint32_t off = sel * 8192 + kc * 2048 + row * 128 + ((u ^ (row & 7)) << 4);
            *(uint4*)(dsm + off) = *(const uint4*)src;
        }
    };

    issueB(0);
    for (int it = 0; it < 72; it++) {
        if (it + 1 < 72) {
            issueB(it + 1);
            asm volatile("cp.async.wait_group 1;");
        } else {
            asm volatile("cp.async.wait_group 0;");
        }
        if ((it & 7) == 0) loadA(it >> 3);
        __syncthreads();

        int buf = it & 1, r = it & 7;
        int sel = r >> 2, kc = r & 3;
        int nA = (sel == 0) ? 2 : 1;
        uint32_t bB = sbase + 16384u + buf * 16384u;
#pragma unroll
        for (int ks = 0; ks < 4; ks++) {
            int u0 = ks * 2 + (lane >> 4);
            uint32_t bb[2][4];
#pragma unroll
            for (int q = 0; q < 2; q++) {
                int row = wn + q * 16 + (lane & 15);
                uint32_t bd = bB + row * 128 + (((unsigned)(u0 ^ (row & 7))) << 4);
                ldmatrix_x4(bb[q][0], bb[q][1], bb[q][2], bb[q][3], bd);
            }
            for (int ai = 0; ai < nA; ai++) {
                uint32_t a[4];
                int row = lane & 15;
                uint32_t ad = sbase + ai * 8192 + kc * 2048 + row * 128 + (((unsigned)(u0 ^ (row & 7))) << 4);
                ldmatrix_x4(a[0], a[1], a[2], a[3], ad);
#pragma unroll
                for (int nj = 0; nj < 4; nj++)
                    mma_bf16(acc[nj], a, bb[nj >> 1][nj & 1], bb[nj >> 1][(nj & 1) + 2]);
            }
        }
        __syncthreads();
    }

    // epilogue: write valid rows (o = 0..8)
    size_t nbase = (size_t)nb * 9 * HW;
    int o0 = lane >> 2;
#pragma unroll
    for (int nj = 0; nj < 4; nj++) {
        int p = p0 + wn + nj * 8 + ((lane & 3) << 1);
        g_l[nbase + (size_t)o0 * HW + p]     = acc[nj][0];
        g_l[nbase + (size_t)o0 * HW + p + 1] = acc[nj][1];
        if (o0 == 0) {
            g_l[nbase + (size_t)8 * HW + p]     = acc[nj][2];
            g_l[nbase + (size_t)8 * HW + p + 1] = acc[nj][3];
        }
    }
}

// ---------------- 2) softmax over 9 taps ----------------
__global__ void __launch_bounds__(256) softmax_kernel()
{
    int id = blockIdx.x * 256 + threadIdx.x;
    int p = id % HW;
    int nb = id / HW;
    float l[9];
#pragma unroll
    for (int o = 0; o < 9; o++)
        l[o] = g_l[((size_t)nb * 9 + o) * HW + p];
    float m = l[0];
#pragma unroll
    for (int o = 1; o < 9; o++) m = fmaxf(m, l[o]);
    float s = 0.f;
#pragma unroll
    for (int o = 0; o < 9; o++) { l[o] = expf(l[o] - m); s += l[o]; }
    float inv = 1.f / s;
#pragma unroll
    for (int o = 0; o < 9; o++)
        g_f[((size_t)nb * 9 + o) * HW + p] = l[o] * inv;
}

// ---------------- 3) HMMA bf16 GEMM (unchanged from round 3) ----------------
__global__ void __launch_bounds__(256, 2) gemm_mma_kernel()
{
    extern __shared__ char dsm[];
    int tid = threadIdx.x;
    int wid = tid >> 5, lane = tid & 31;
    int pbase = blockIdx.x * 128;
    int mbase = blockIdx.y * 128;
    int bn = blockIdx.z;
    int b = bn >> 1, n = bn & 1;
    int warp_m = wid & 1, warp_n = wid >> 1;

    uint32_t sbase = smem_u32(dsm);
    const uint32_t offA[2] = { 0u, 32768u };
    const uint32_t offB[2] = { 16384u, 49152u };

    float acc[4][4][4];
#pragma unroll
    for (int i = 0; i < 4; i++)
#pragma unroll
        for (int j = 0; j < 4; j++)
#pragma unroll
            for (int r = 0; r < 4; r++) acc[i][j][r] = 0.f;

    auto issue = [&](int i) {
        int buf = i & 1;
        int seg = i >> 2, kc = i & 3;
        int aSel = (seg == 1) ? 1 : 0;
        int bSel = (seg == 2) ? 1 : 0;
        const char* Ag = (const char*)g_w  + ((size_t)((b * 2 + aSel) * 256 + mbase)) * 512 + kc * 128;
        const char* Bg = (const char*)g_xT + ((size_t)((n * 2 + bSel) * HW + pbase)) * 512 + kc * 128;
#pragma unroll
        for (int r = 0; r < 4; r++) {
            int idx = tid + 256 * r;
            int row = idx >> 3, u = idx & 7;
            uint32_t sw = row * 128 + ((u ^ (row & 7)) << 4);
            cp_async16(sbase + offA[buf] + sw, Ag + (size_t)row * 512 + u * 16);
            cp_async16(sbase + offB[buf] + sw, Bg + (size_t)row * 512 + u * 16);
        }
        asm volatile("cp.async.commit_group;");
    };

    auto compute = [&](int buf) {
        uint32_t aB = sbase + offA[buf];
        uint32_t bB = sbase + offB[buf];
#pragma unroll
        for (int ks = 0; ks < 4; ks++) {
            int u0 = ks * 2 + (lane >> 4);
            uint32_t a[4][4], bb[2][4];
#pragma unroll
            for (int mi = 0; mi < 4; mi++) {
                int row = warp_m * 64 + mi * 16 + (lane & 15);
                uint32_t ad = aB + row * 128 + (((unsigned)(u0 ^ (row & 7))) << 4);
                ldmatrix_x4(a[mi][0], a[mi][1], a[mi][2], a[mi][3], ad);
            }
#pragma unroll
            for (int q = 0; q < 2; q++) {
                int row = warp_n * 32 + q * 16 + (lane & 15);
                uint32_t bd = bB + row * 128 + (((unsigned)(u0 ^ (row & 7))) << 4);
                ldmatrix_x4(bb[q][0], bb[q][1], bb[q][2], bb[q][3], bd);
            }
#pragma unroll
            for (int mi = 0; mi < 4; mi++)
#pragma unroll
                for (int nj = 0; nj < 4; nj++) {
                    int q = nj >> 1, pr = nj & 1;
                    mma_bf16(acc[mi][nj], a[mi], bb[q][pr], bb[q][pr + 2]);
                }
        }
    };

    issue(0);
    for (int i = 0; i < 12; i++) {
        if (i < 11) {
            issue(i + 1);
            asm volatile("cp.async.wait_group 1;");
        } else {
            asm volatile("cp.async.wait_group 0;");
        }
        __syncthreads();
        compute(i & 1);
        __syncthreads();
    }

    float* stage = (float*)dsm;
#pragma unroll
    for (int mi = 0; mi < 4; mi++)
#pragma unroll
        for (int nj = 0; nj < 4; nj++)
#pragma unroll
            for (int r = 0; r < 4; r++) {
                int p = warp_n * 32 + nj * 8 + 2 * (lane & 3) + (r & 1);
                int m = warp_m * 64 + mi * 16 + (lane >> 2) + ((r >> 1) << 3);
                stage[p * 132 + m] = acc[mi][nj][r];
            }
    __syncthreads();
    float* zo = (float*)g_z + ((size_t)bn * HW + pbase) * 256 + mbase;
#pragma unroll
    for (int r = 0; r < 16; r++) {
        int idx = tid + 256 * r;
        int px = idx >> 5, c4 = (idx & 31) * 4;
        float4 v = *(float4*)&stage[px * 132 + c4];
        *(float4*)(zo + (size_t)px * 256 + c4) = v;
    }
}

// ---------------- 4) combine, coalesced: warp-half per pixel ----------------
// grid (1152, 2), block 512: warp w -> pixel p0 + w/2, channels (w%2)*128 + lane*4
__global__ void __launch_bounds__(512) combine_kernel(const float* __restrict__ bias)
{
    int tid = threadIdx.x;
    int n = blockIdx.y;
    int p0 = blockIdx.x * 8;
    int warp = tid >> 5, lane = tid & 31;
    int pi = warp >> 1, half = warp & 1;
    int p = p0 + pi;
    int c = half * 128 + lane * 4;

    __shared__ float fsw[8][40];
    __shared__ int   pofs[8][40];
    __shared__ float bp_s[16][16];
    __shared__ float bp_q[16][16];

    if (tid < 288) {
        int pi2 = tid / 36, j = tid - pi2 * 36;
        int br = j / 9, k = j - br * 9;
        int d = (br == 0) ? 1 : (br == 1) ? 4 : (br == 2) ? 8 : 12;
        int pg = p0 + pi2;
        int yy = pg / 96 + (k / 3 - 1) * d;
        int xx = pg % 96 + (k % 3 - 1) * d;
        bool v = ((unsigned)yy < 96u) && ((unsigned)xx < 96u);
        fsw[pi2][j]  = v ? g_f[((size_t)(n * 4 + br) * 9 + k) * HW + pg] : 0.f;
        pofs[pi2][j] = (((br + 1) * 2 + n) * HW + (v ? (yy * 96 + xx) : 0)) * 256;
    }
    __syncthreads();

    float4 b4 = *(const float4*)(bias + c);
    float4 z4 = *(const float4*)(g_z + ((size_t)n * HW + p) * 256 + c);
    float a0 = z4.x + b4.x, a1 = z4.y + b4.y, a2 = z4.z + b4.z, a3 = z4.w + b4.w;

#pragma unroll 4
    for (int j = 0; j < 36; j++) {
        float f = fsw[pi][j];
        const float* zp = g_z + (size_t)pofs[pi][j] + c;
        float4 v = *(const float4*)zp;
        a0 = fmaf(f, v.x, a0); a1 = fmaf(f, v.y, a1);
        a2 = fmaf(f, v.z, a2); a3 = fmaf(f, v.w, a3);
    }
    *(float4*)(g_y + ((size_t)n * HW + p) * 256 + c) = make_float4(a0, a1, a2, a3);

    float s = a0 + a1 + a2 + a3;
    float q = a0 * a0 + a1 * a1 + a2 * a2 + a3 * a3;
    s += __shfl_xor_sync(0xffffffffu, s, 1);
    q += __shfl_xor_sync(0xffffffffu, q, 1);
    if ((lane & 1) == 0) { bp_s[warp][lane >> 1] = s; bp_q[warp][lane >> 1] = q; }
    __syncthreads();
    if (tid < 64) {
        int g = tid >> 1, isq = tid & 1;
        int hf = g >> 4, gi = g & 15;
        float acc = 0.f;
#pragma unroll
        for (int pi2 = 0; pi2 < 8; pi2++)
            acc += isq ? bp_q[pi2 * 2 + hf][gi] : bp_s[pi2 * 2 + hf][gi];
        g_bpart[((size_t)n * 1152 + blockIdx.x) * 64 + tid] = acc;
    }
}

// ---------------- 5) GN stats ----------------
__global__ void __launch_bounds__(128) stats_kernel()
{
    int b = blockIdx.x;          // n*32+g
    int n = b >> 5, g = b & 31;
    int tid = threadIdx.x;
    float s = 0.f, q = 0.f;
    for (int i = tid; i < 1152; i += 128) {
        size_t base = ((size_t)n * 1152 + i) * 64 + g * 2;
        s += g_bpart[base];
        q += g_bpart[base + 1];
    }
    __shared__ float ss[128], sq[128];
    ss[tid] = s; sq[tid] = q;
    __syncthreads();
    for (int off = 64; off > 0; off >>= 1) {
        if (tid < off) { ss[tid] += ss[tid + off]; sq[tid] += sq[tid + off]; }
        __syncthreads();
    }
    if (tid == 0) {
        const float invN = 1.f / 73728.f;
        float mean = ss[0] * invN;
        float var  = sq[0] * invN - mean * mean;
        g_stats[b * 2]     = mean;
        g_stats[b * 2 + 1] = rsqrtf(var + 1e-5f);
    }
}

// ---------------- 6) transpose [p][c]->[c][p] + GN affine + relu ----------------
__global__ void __launch_bounds__(256) normT_kernel(
    const float* __restrict__ gamma, const float* __restrict__ beta,
    float* __restrict__ out)
{
    __shared__ float t[32][33];
    int p0 = blockIdx.x * 32, c0 = blockIdx.y * 32, n = blockIdx.z;
    int tx = threadIdx.x, ty = threadIdx.y;
#pragma unroll
    for (int r = 0; r < 4; r++)
        t[ty + 8 * r][tx] = g_y[((size_t)n * HW + p0 + ty + 8 * r) * 256 + c0 + tx];
    __syncthreads();
#pragma unroll
    for (int r = 0; r < 4; r++) {
        int c = c0 + ty + 8 * r, p = p0 + tx;
        int g = c >> 3;
        float mean = g_stats[(n * 32 + g) * 2];
        float rstd = g_stats[(n * 32 + g) * 2 + 1];
        float ga = gamma[c] * rstd;
        float be = beta[c] - mean * ga;
        float v = t[tx][ty + 8 * r];
        out[((size_t)n * 256 + c) * HW + p] = fmaxf(fmaf(v, ga, be), 0.f);
    }
}

// ---------------- launch ----------------
extern "C" void kernel_launch(void* const* d_in, const int* in_sizes, int n_in,
                              void* d_out, int out_size)
{
    const float* x     = (const float*)d_in[0];
    const float* wa    = (const float*)d_in[1];
    const float* wb    = (const float*)d_in[2];
    const float* wc    = (const float*)d_in[3];
    const float* wd    = (const float*)d_in[4];
    const float* wproj = (const float*)d_in[5];
    const float* bproj = (const float*)d_in[6];
    const float* gamma = (const float*)d_in[7];
    const float* beta  = (const float*)d_in[8];
    float* out = (float*)d_out;

    cudaFuncSetAttribute(gemm_mma_kernel, cudaFuncAttributeMaxDynamicSharedMemorySize, 69632);
    cudaFuncSetAttribute(logits_mma_kernel, cudaFuncAttributeMaxDynamicSharedMemorySize, 49152);

    wsplit_kernel<<<1280, 256>>>(wproj);
    wlsplit_kernel<<<1152, 256>>>(wa, wb, wc, wd);
    xsplit_kernel<<<dim3(288, 8, 2), dim3(32, 8)>>>(x);
    logits_mma_kernel<<<dim3(72, 8), 128, 49152>>>();
    softmax_kernel<<<288, 256>>>();
    gemm_mma_kernel<<<dim3(72, 2, 10), 256, 69632>>>();
    combine_kernel<<<dim3(1152, 2), 512>>>(bproj);
    stats_kernel<<<64, 128>>>();
    normT_kernel<<<dim3(288, 8, 2), dim3(32, 8)>>>(gamma, beta, out);
}

// round 5
// speedup vs baseline: 3.3410x; 1.5770x over previous
#include <cuda_runtime.h>
#include <cuda_bf16.h>
#include <cstdint>
#include <math.h>

#define HW    9216
#define CH    256
#define NB    2

// ---------------- scratch ----------------
__device__ float g_f[8ull * 9 * HW];               // [nb][o][HW] softmax tap weights
__device__ float g_u[(size_t)NB * 384 * HW];       // [n][br*96 + o*9+tap][HW] untapped logits
__device__ float g_z[10ull * HW * CH + 400000];    // [b*2+n][p][c]
__device__ float g_y[(size_t)NB * HW * CH];        // [n][p][c] pre-GN output
__device__ float g_bpart[NB * 1152 * 64];
__device__ float g_stats[NB * 32 * 2];
__device__ __nv_bfloat16 g_w[10ull * 256 * 256];   // [b*2+sel][m][k]
__device__ __nv_bfloat16 g_xT[4ull * HW * 256];    // [n*2+sel][p][k]
__device__ __nv_bfloat16 g_wl2[384ull * 768];      // [m=br*96+o*9+tap][k=768: hi|lo|hi]

// ---------------- helpers ----------------
__device__ __forceinline__ uint32_t smem_u32(const void* p) {
    uint32_t a;
    asm("{ .reg .u64 t; cvta.to.shared.u64 t, %1; cvt.u32.u64 %0, t; }" : "=r"(a) : "l"(p));
    return a;
}
__device__ __forceinline__ void ldmatrix_x4(uint32_t& r0, uint32_t& r1, uint32_t& r2, uint32_t& r3, uint32_t addr) {
    asm volatile("ldmatrix.sync.aligned.m8n8.x4.shared.b16 {%0,%1,%2,%3}, [%4];"
        : "=r"(r0), "=r"(r1), "=r"(r2), "=r"(r3) : "r"(addr));
}
__device__ __forceinline__ void mma_bf16(float* c, const uint32_t* a, uint32_t b0, uint32_t b1) {
    asm volatile("mma.sync.aligned.m16n8k16.row.col.f32.bf16.bf16.f32 "
        "{%0,%1,%2,%3}, {%4,%5,%6,%7}, {%8,%9}, {%0,%1,%2,%3};"
        : "+f"(c[0]), "+f"(c[1]), "+f"(c[2]), "+f"(c[3])
        : "r"(a[0]), "r"(a[1]), "r"(a[2]), "r"(a[3]), "r"(b0), "r"(b1));
}
__device__ __forceinline__ void cp_async16(uint32_t saddr, const void* gaddr) {
    asm volatile("cp.async.cg.shared.global [%0], [%1], 16;" :: "r"(saddr), "l"(gaddr));
}

// ---------------- prep: split W (proj) into bf16 hi/lo ----------------
__global__ void __launch_bounds__(256) wsplit_kernel(const float* __restrict__ wproj)
{
    int idx = blockIdx.x * 256 + threadIdx.x;
    if (idx >= 5 * 65536) return;
    int b = idx >> 16, rem = idx & 65535;
    int m = rem >> 8, k = rem & 255;
    float w = wproj[m * 1280 + b * 256 + k];
    __nv_bfloat16 hi = __float2bfloat16(w);
    __nv_bfloat16 lo = __float2bfloat16(w - __bfloat162float(hi));
    g_w[((size_t)(b * 2 + 0) * 256 + m) * 256 + k] = hi;
    g_w[((size_t)(b * 2 + 1) * 256 + m) * 256 + k] = lo;
}

// ---------------- prep: logits weights -> A[384][768] ----------------
__global__ void __launch_bounds__(256) wl2split_kernel(
    const float* __restrict__ wa, const float* __restrict__ wb,
    const float* __restrict__ wc, const float* __restrict__ wd)
{
    int idx = blockIdx.x * 256 + threadIdx.x;       // 384*768 = 294912
    if (idx >= 294912) return;
    int k = idx % 768, m = idx / 768;
    int br = m / 96, row = m - br * 96;
    int seg = k >> 8, c = k & 255;
    float w = 0.f;
    if (row < 81) {
        int o = row / 9, tap = row - o * 9;
        const float* wp = (br == 0) ? wa : (br == 1) ? wb : (br == 2) ? wc : wd;
        w = wp[(o * 256 + c) * 9 + tap];
    }
    __nv_bfloat16 hi = __float2bfloat16(w);
    __nv_bfloat16 v = (seg == 1) ? __float2bfloat16(w - __bfloat162float(hi)) : hi;
    g_wl2[(size_t)m * 768 + k] = v;
}

// ---------------- prep: transpose x to [p][k] + bf16 hi/lo ----------------
__global__ void __launch_bounds__(256) xsplit_kernel(const float* __restrict__ x)
{
    __shared__ float t[32][33];
    int p0 = blockIdx.x * 32, k0 = blockIdx.y * 32, n = blockIdx.z;
    int tx = threadIdx.x, ty = threadIdx.y;
#pragma unroll
    for (int r = 0; r < 4; r++)
        t[ty + 8 * r][tx] = x[((size_t)(n * 256 + k0 + ty + 8 * r)) * HW + p0 + tx];
    __syncthreads();
#pragma unroll
    for (int r = 0; r < 4; r++) {
        int p = p0 + ty + 8 * r, k = k0 + tx;
        float v = t[tx][ty + 8 * r];
        __nv_bfloat16 hi = __float2bfloat16(v);
        __nv_bfloat16 lo = __float2bfloat16(v - __bfloat162float(hi));
        g_xT[((size_t)(n * 2 + 0) * HW + p) * 256 + k] = hi;
        g_xT[((size_t)(n * 2 + 1) * HW + p) * 256 + k] = lo;
    }
}

// ---------------- 1) U-GEMM: U[384,HW] = A_logits @ X (per n) ----------------
// grid (72 p-tiles, 3 m-tiles, 2 n), block 256
__global__ void __launch_bounds__(256, 2) gemm_u_kernel()
{
    extern __shared__ char dsm[];
    int tid = threadIdx.x;
    int wid = tid >> 5, lane = tid & 31;
    int pbase = blockIdx.x * 128;
    int mbase = blockIdx.y * 128;
    int n = blockIdx.z;
    int warp_m = wid & 1, warp_n = wid >> 1;

    uint32_t sbase = smem_u32(dsm);
    const uint32_t offA[2] = { 0u, 32768u };
    const uint32_t offB[2] = { 16384u, 49152u };

    float acc[4][4][4];
#pragma unroll
    for (int i = 0; i < 4; i++)
#pragma unroll
        for (int j = 0; j < 4; j++)
#pragma unroll
            for (int r = 0; r < 4; r++) acc[i][j][r] = 0.f;

    auto issue = [&](int i) {
        int buf = i & 1;
        int seg = i >> 2, kc = i & 3;
        int bSel = (seg == 2) ? 1 : 0;
        const char* Ag = (const char*)g_wl2 + (size_t)mbase * 1536 + i * 128;
        const char* Bg = (const char*)g_xT + ((size_t)((n * 2 + bSel) * HW + pbase)) * 512 + kc * 128;
#pragma unroll
        for (int r = 0; r < 4; r++) {
            int idx = tid + 256 * r;
            int row = idx >> 3, u = idx & 7;
            uint32_t sw = row * 128 + ((u ^ (row & 7)) << 4);
            cp_async16(sbase + offA[buf] + sw, Ag + (size_t)row * 1536 + u * 16);
            cp_async16(sbase + offB[buf] + sw, Bg + (size_t)row * 512 + u * 16);
        }
        asm volatile("cp.async.commit_group;");
    };

    auto compute = [&](int buf) {
        uint32_t aB = sbase + offA[buf];
        uint32_t bB = sbase + offB[buf];
#pragma unroll
        for (int ks = 0; ks < 4; ks++) {
            int u0 = ks * 2 + (lane >> 4);
            uint32_t a[4][4], bb[2][4];
#pragma unroll
            for (int mi = 0; mi < 4; mi++) {
                int row = warp_m * 64 + mi * 16 + (lane & 15);
                uint32_t ad = aB + row * 128 + (((unsigned)(u0 ^ (row & 7))) << 4);
                ldmatrix_x4(a[mi][0], a[mi][1], a[mi][2], a[mi][3], ad);
            }
#pragma unroll
            for (int q = 0; q < 2; q++) {
                int row = warp_n * 32 + q * 16 + (lane & 15);
                uint32_t bd = bB + row * 128 + (((unsigned)(u0 ^ (row & 7))) << 4);
                ldmatrix_x4(bb[q][0], bb[q][1], bb[q][2], bb[q][3], bd);
            }
#pragma unroll
            for (int mi = 0; mi < 4; mi++)
#pragma unroll
                for (int nj = 0; nj < 4; nj++) {
                    int q = nj >> 1, pr = nj & 1;
                    mma_bf16(acc[mi][nj], a[mi], bb[q][pr], bb[q][pr + 2]);
                }
        }
    };

    issue(0);
    for (int i = 0; i < 12; i++) {
        if (i < 11) {
            issue(i + 1);
            asm volatile("cp.async.wait_group 1;");
        } else {
            asm volatile("cp.async.wait_group 0;");
        }
        __syncthreads();
        compute(i & 1);
        __syncthreads();
    }

    // epilogue: stage[p][m] -> g_u[m][p] coalesced
    float* stage = (float*)dsm;
#pragma unroll
    for (int mi = 0; mi < 4; mi++)
#pragma unroll
        for (int nj = 0; nj < 4; nj++)
#pragma unroll
            for (int r = 0; r < 4; r++) {
                int p = warp_n * 32 + nj * 8 + 2 * (lane & 3) + (r & 1);
                int m = warp_m * 64 + mi * 16 + (lane >> 2) + ((r >> 1) << 3);
                stage[p * 132 + m] = acc[mi][nj][r];
            }
    __syncthreads();
#pragma unroll
    for (int rr = 0; rr < 16; rr++) {
        int idx = tid + 256 * rr;          // 0..4095
        int m = idx >> 5, p4 = (idx & 31) * 4;
        float4 v = make_float4(stage[p4 * 132 + m], stage[(p4 + 1) * 132 + m],
                               stage[(p4 + 2) * 132 + m], stage[(p4 + 3) * 132 + m]);
        *(float4*)(g_u + ((size_t)n * 384 + mbase + m) * HW + pbase + p4) = v;
    }
}

// ---------------- 2) gather taps + softmax ----------------
__global__ void __launch_bounds__(256) gathersoftmax_kernel()
{
    int id = blockIdx.x * 256 + threadIdx.x;     // 8*HW
    int p = id % HW;
    int nb = id / HW;
    int n = nb >> 2, br = nb & 3;
    int d = (br == 0) ? 1 : (br == 1) ? 4 : (br == 2) ? 8 : 12;
    int y = p / 96, x = p - y * 96;

    int po[9];
#pragma unroll
    for (int t = 0; t < 9; t++) {
        int yy = y + (t / 3 - 1) * d;
        int xx = x + (t % 3 - 1) * d;
        po[t] = (((unsigned)yy < 96u) && ((unsigned)xx < 96u)) ? (yy * 96 + xx) : -1;
    }

    const float* ub = g_u + ((size_t)n * 384 + br * 96) * HW;
    float l[9];
#pragma unroll
    for (int o = 0; o < 9; o++) {
        float s = 0.f;
#pragma unroll
        for (int t = 0; t < 9; t++)
            if (po[t] >= 0) s += ub[(size_t)(o * 9 + t) * HW + po[t]];
        l[o] = s;
    }
    float m = l[0];
#pragma unroll
    for (int o = 1; o < 9; o++) m = fmaxf(m, l[o]);
    float s = 0.f;
#pragma unroll
    for (int o = 0; o < 9; o++) { l[o] = expf(l[o] - m); s += l[o]; }
    float inv = 1.f / s;
#pragma unroll
    for (int o = 0; o < 9; o++)
        g_f[((size_t)nb * 9 + o) * HW + p] = l[o] * inv;
}

// ---------------- 3) HMMA bf16 proj GEMM (unchanged) ----------------
__global__ void __launch_bounds__(256, 2) gemm_mma_kernel()
{
    extern __shared__ char dsm[];
    int tid = threadIdx.x;
    int wid = tid >> 5, lane = tid & 31;
    int pbase = blockIdx.x * 128;
    int mbase = blockIdx.y * 128;
    int bn = blockIdx.z;
    int b = bn >> 1, n = bn & 1;
    int warp_m = wid & 1, warp_n = wid >> 1;

    uint32_t sbase = smem_u32(dsm);
    const uint32_t offA[2] = { 0u, 32768u };
    const uint32_t offB[2] = { 16384u, 49152u };

    float acc[4][4][4];
#pragma unroll
    for (int i = 0; i < 4; i++)
#pragma unroll
        for (int j = 0; j < 4; j++)
#pragma unroll
            for (int r = 0; r < 4; r++) acc[i][j][r] = 0.f;

    auto issue = [&](int i) {
        int buf = i & 1;
        int seg = i >> 2, kc = i & 3;
        int aSel = (seg == 1) ? 1 : 0;
        int bSel = (seg == 2) ? 1 : 0;
        const char* Ag = (const char*)g_w  + ((size_t)((b * 2 + aSel) * 256 + mbase)) * 512 + kc * 128;
        const char* Bg = (const char*)g_xT + ((size_t)((n * 2 + bSel) * HW + pbase)) * 512 + kc * 128;
#pragma unroll
        for (int r = 0; r < 4; r++) {
            int idx = tid + 256 * r;
            int row = idx >> 3, u = idx & 7;
            uint32_t sw = row * 128 + ((u ^ (row & 7)) << 4);
            cp_async16(sbase + offA[buf] + sw, Ag + (size_t)row * 512 + u * 16);
            cp_async16(sbase + offB[buf] + sw, Bg + (size_t)row * 512 + u * 16);
        }
        asm volatile("cp.async.commit_group;");
    };

    auto compute = [&](int buf) {
        uint32_t aB = sbase + offA[buf];
        uint32_t bB = sbase + offB[buf];
#pragma unroll
        for (int ks = 0; ks < 4; ks++) {
            int u0 = ks * 2 + (lane >> 4);
            uint32_t a[4][4], bb[2][4];
#pragma unroll
            for (int mi = 0; mi < 4; mi++) {
                int row = warp_m * 64 + mi * 16 + (lane & 15);
                uint32_t ad = aB + row * 128 + (((unsigned)(u0 ^ (row & 7))) << 4);
                ldmatrix_x4(a[mi][0], a[mi][1], a[mi][2], a[mi][3], ad);
            }
#pragma unroll
            for (int q = 0; q < 2; q++) {
                int row = warp_n * 32 + q * 16 + (lane & 15);
                uint32_t bd = bB + row * 128 + (((unsigned)(u0 ^ (row & 7))) << 4);
                ldmatrix_x4(bb[q][0], bb[q][1], bb[q][2], bb[q][3], bd);
            }
#pragma unroll
            for (int mi = 0; mi < 4; mi++)
#pragma unroll
                for (int nj = 0; nj < 4; nj++) {
                    int q = nj >> 1, pr = nj & 1;
                    mma_bf16(acc[mi][nj], a[mi], bb[q][pr], bb[q][pr + 2]);
                }
        }
    };

    issue(0);
    for (int i = 0; i < 12; i++) {
        if (i < 11) {
            issue(i + 1);
            asm volatile("cp.async.wait_group 1;");
        } else {
            asm volatile("cp.async.wait_group 0;");
        }
        __syncthreads();
        compute(i & 1);
        __syncthreads();
    }

    float* stage = (float*)dsm;
#pragma unroll
    for (int mi = 0; mi < 4; mi++)
#pragma unroll
        for (int nj = 0; nj < 4; nj++)
#pragma unroll
            for (int r = 0; r < 4; r++) {
                int p = warp_n * 32 + nj * 8 + 2 * (lane & 3) + (r & 1);
                int m = warp_m * 64 + mi * 16 + (lane >> 2) + ((r >> 1) << 3);
                stage[p * 132 + m] = acc[mi][nj][r];
            }
    __syncthreads();
    float* zo = (float*)g_z + ((size_t)bn * HW + pbase) * 256 + mbase;
#pragma unroll
    for (int r = 0; r < 16; r++) {
        int idx = tid + 256 * r;
        int px = idx >> 5, c4 = (idx & 31) * 4;
        float4 v = *(float4*)&stage[px * 132 + c4];
        *(float4*)(zo + (size_t)px * 256 + c4) = v;
    }
}

// ---------------- 4) combine, coalesced (unchanged) ----------------
__global__ void __launch_bounds__(512) combine_kernel(const float* __restrict__ bias)
{
    int tid = threadIdx.x;
    int n = blockIdx.y;
    int p0 = blockIdx.x * 8;
    int warp = tid >> 5, lane = tid & 31;
    int pi = warp >> 1, half = warp & 1;
    int p = p0 + pi;
    int c = half * 128 + lane * 4;

    __shared__ float fsw[8][40];
    __shared__ int   pofs[8][40];
    __shared__ float bp_s[16][16];
    __shared__ float bp_q[16][16];

    if (tid < 288) {
        int pi2 = tid / 36, j = tid - pi2 * 36;
        int br = j / 9, k = j - br * 9;
        int d = (br == 0) ? 1 : (br == 1) ? 4 : (br == 2) ? 8 : 12;
        int pg = p0 + pi2;
        int yy = pg / 96 + (k / 3 - 1) * d;
        int xx = pg % 96 + (k % 3 - 1) * d;
        bool v = ((unsigned)yy < 96u) && ((unsigned)xx < 96u);
        fsw[pi2][j]  = v ? g_f[((size_t)(n * 4 + br) * 9 + k) * HW + pg] : 0.f;
        pofs[pi2][j] = (((br + 1) * 2 + n) * HW + (v ? (yy * 96 + xx) : 0)) * 256;
    }
    __syncthreads();

    float4 b4 = *(const float4*)(bias + c);
    float4 z4 = *(const float4*)(g_z + ((size_t)n * HW + p) * 256 + c);
    float a0 = z4.x + b4.x, a1 = z4.y + b4.y, a2 = z4.z + b4.z, a3 = z4.w + b4.w;

#pragma unroll 4
    for (int j = 0; j < 36; j++) {
        float f = fsw[pi][j];
        const float* zp = g_z + (size_t)pofs[pi][j] + c;
        float4 v = *(const float4*)zp;
        a0 = fmaf(f, v.x, a0); a1 = fmaf(f, v.y, a1);
        a2 = fmaf(f, v.z, a2); a3 = fmaf(f, v.w, a3);
    }
    *(float4*)(g_y + ((size_t)n * HW + p) * 256 + c) = make_float4(a0, a1, a2, a3);

    float s = a0 + a1 + a2 + a3;
    float q = a0 * a0 + a1 * a1 + a2 * a2 + a3 * a3;
    s += __shfl_xor_sync(0xffffffffu, s, 1);
    q += __shfl_xor_sync(0xffffffffu, q, 1);
    if ((lane & 1) == 0) { bp_s[warp][lane >> 1] = s; bp_q[warp][lane >> 1] = q; }
    __syncthreads();
    if (tid < 64) {
        int g = tid >> 1, isq = tid & 1;
        int hf = g >> 4, gi = g & 15;
        float acc = 0.f;
#pragma unroll
        for (int pi2 = 0; pi2 < 8; pi2++)
            acc += isq ? bp_q[pi2 * 2 + hf][gi] : bp_s[pi2 * 2 + hf][gi];
        g_bpart[((size_t)n * 1152 + blockIdx.x) * 64 + tid] = acc;
    }
}

// ---------------- 5) GN stats ----------------
__global__ void __launch_bounds__(128) stats_kernel()
{
    int b = blockIdx.x;
    int n = b >> 5, g = b & 31;
    int tid = threadIdx.x;
    float s = 0.f, q = 0.f;
    for (int i = tid; i < 1152; i += 128) {
        size_t base = ((size_t)n * 1152 + i) * 64 + g * 2;
        s += g_bpart[base];
        q += g_bpart[base + 1];
    }
    __shared__ float ss[128], sq[128];
    ss[tid] = s; sq[tid] = q;
    __syncthreads();
    for (int off = 64; off > 0; off >>= 1) {
        if (tid < off) { ss[tid] += ss[tid + off]; sq[tid] += sq[tid + off]; }
        __syncthreads();
    }
    if (tid == 0) {
        const float invN = 1.f / 73728.f;
        float mean = ss[0] * invN;
        float var  = sq[0] * invN - mean * mean;
        g_stats[b * 2]     = mean;
        g_stats[b * 2 + 1] = rsqrtf(var + 1e-5f);
    }
}

// ---------------- 6) transpose + GN affine + relu ----------------
__global__ void __launch_bounds__(256) normT_kernel(
    const float* __restrict__ gamma, const float* __restrict__ beta,
    float* __restrict__ out)
{
    __shared__ float t[32][33];
    int p0 = blockIdx.x * 32, c0 = blockIdx.y * 32, n = blockIdx.z;
    int tx = threadIdx.x, ty = threadIdx.y;
#pragma unroll
    for (int r = 0; r < 4; r++)
        t[ty + 8 * r][tx] = g_y[((size_t)n * HW + p0 + ty + 8 * r) * 256 + c0 + tx];
    __syncthreads();
#pragma unroll
    for (int r = 0; r < 4; r++) {
        int c = c0 + ty + 8 * r, p = p0 + tx;
        int g = c >> 3;
        float mean = g_stats[(n * 32 + g) * 2];
        float rstd = g_stats[(n * 32 + g) * 2 + 1];
        float ga = gamma[c] * rstd;
        float be = beta[c] - mean * ga;
        float v = t[tx][ty + 8 * r];
        out[((size_t)n * 256 + c) * HW + p] = fmaxf(fmaf(v, ga, be), 0.f);
    }
}

// ---------------- launch ----------------
extern "C" void kernel_launch(void* const* d_in, const int* in_sizes, int n_in,
                              void* d_out, int out_size)
{
    const float* x     = (const float*)d_in[0];
    const float* wa    = (const float*)d_in[1];
    const float* wb    = (const float*)d_in[2];
    const float* wc    = (const float*)d_in[3];
    const float* wd    = (const float*)d_in[4];
    const float* wproj = (const float*)d_in[5];
    const float* bproj = (const float*)d_in[6];
    const float* gamma = (const float*)d_in[7];
    const float* beta  = (const float*)d_in[8];
    float* out = (float*)d_out;

    cudaFuncSetAttribute(gemm_mma_kernel, cudaFuncAttributeMaxDynamicSharedMemorySize, 69632);
    cudaFuncSetAttribute(gemm_u_kernel,   cudaFuncAttributeMaxDynamicSharedMemorySize, 69632);

    wsplit_kernel<<<1280, 256>>>(wproj);
    wl2split_kernel<<<1152, 256>>>(wa, wb, wc, wd);
    xsplit_kernel<<<dim3(288, 8, 2), dim3(32, 8)>>>(x);
    gemm_u_kernel<<<dim3(72, 3, 2), 256, 69632>>>();
    gathersoftmax_kernel<<<288, 256>>>();
    gemm_mma_kernel<<<dim3(72, 2, 10), 256, 69632>>>();
    combine_kernel<<<dim3(1152, 2), 512>>>(bproj);
    stats_kernel<<<64, 128>>>();
    normT_kernel<<<dim3(288, 8, 2), dim3(32, 8)>>>(gamma, beta, out);
}